// round 1
// baseline (speedup 1.0000x reference)
#include <cuda_runtime.h>
#include <cuda_bf16.h>
#include <cstdint>

#define NN 50000
#define EE 800000
#define FDIM 128
#define HID 128
#define NCAT 384   // [W_src | W_dst | W_lin]
#define NHEAD 4
#define LRELU 0.2f
#define LN_EPS 1e-5f

// ------------------------- scratch (device globals; no allocs allowed) -----
__device__ float g_xsxd[(size_t)NN * 256];   // per row: [xs(128) | xd(128)]
__device__ float g_acc1[(size_t)NN * 128];   // layer1 accumulator (lin+bias, then +gat)
__device__ float g_h[(size_t)NN * 128];      // layer1 output after LN+ReLU
__device__ float g_w[(size_t)EE * NHEAD];    // per-edge exp weights
__device__ float g_as[NN * NHEAD];
__device__ float g_ad[NN * NHEAD];
__device__ float g_denom[NN * NHEAD];
__device__ float g_Wcat[FDIM * NCAT];        // packed weights [K=128, 384]
__device__ float g_bias[128];                // bl + b_gat

// ------------------------- weight packing --------------------------------
__global__ void pack_w(const float* __restrict__ Wsrc, const float* __restrict__ Wdst,
                       const float* __restrict__ Wl, const float* __restrict__ bl,
                       const float* __restrict__ bg)
{
    int i = blockIdx.x * blockDim.x + threadIdx.x;
    if (i < 128 * 128) {
        int k = i >> 7, c = i & 127;
        g_Wcat[k * NCAT + c]       = Wsrc[i];
        g_Wcat[k * NCAT + 128 + c] = Wdst[i];
        g_Wcat[k * NCAT + 256 + c] = Wl[i];
    }
    if (i < 128) g_bias[i] = bl[i] + bg[i];
}

// ------------------------- fused SGEMM: A[M,128] @ Wcat[128,384] ----------
// cols [0,256) -> g_xsxd (stride 256); cols [256,384) -> acc (stride 128, +bias)
#define TM 64
#define TN 64
#define KC 32

__global__ __launch_bounds__(256) void sgemm_pack(const float* __restrict__ A,
                                                  float* __restrict__ acc, int M)
{
    __shared__ float As[KC][TM + 4];
    __shared__ float Bs[KC][TN + 4];
    const int row0 = blockIdx.x * TM;
    const int col0 = blockIdx.y * TN;
    const int tid = threadIdx.x;
    const int tx = tid & 15, ty = tid >> 4;

    float accr[4][4] = {};

    for (int k0 = 0; k0 < 128; k0 += KC) {
        // load A tile 64x32 (transposed into smem)
        {
            int r  = tid >> 3;           // 0..31
            int kv = (tid & 7) * 4;      // 0..28
            #pragma unroll
            for (int rr = 0; rr < 2; rr++) {
                int row = row0 + r + rr * 32;
                float4 v = make_float4(0.f, 0.f, 0.f, 0.f);
                if (row < M) v = *(const float4*)(A + (size_t)row * 128 + k0 + kv);
                As[kv + 0][r + rr * 32] = v.x;
                As[kv + 1][r + rr * 32] = v.y;
                As[kv + 2][r + rr * 32] = v.z;
                As[kv + 3][r + rr * 32] = v.w;
            }
        }
        // load B tile 32x64
        {
            int k  = tid >> 4;           // 0..15
            int cv = (tid & 15) * 4;
            #pragma unroll
            for (int kk2 = 0; kk2 < 2; kk2++) {
                float4 v = *(const float4*)(g_Wcat + (size_t)(k0 + k + kk2 * 16) * NCAT + col0 + cv);
                *(float4*)&Bs[k + kk2 * 16][cv] = v;
            }
        }
        __syncthreads();
        #pragma unroll
        for (int kk = 0; kk < KC; kk++) {
            float a[4], b[4];
            *(float4*)a = *(const float4*)&As[kk][ty * 4];
            *(float4*)b = *(const float4*)&Bs[kk][tx * 4];
            #pragma unroll
            for (int i = 0; i < 4; i++)
                #pragma unroll
                for (int j = 0; j < 4; j++)
                    accr[i][j] = fmaf(a[i], b[j], accr[i][j]);
        }
        __syncthreads();
    }

    if (col0 < 256) {
        #pragma unroll
        for (int i = 0; i < 4; i++) {
            int row = row0 + ty * 4 + i;
            if (row < M) {
                float4 v = make_float4(accr[i][0], accr[i][1], accr[i][2], accr[i][3]);
                *(float4*)(g_xsxd + (size_t)row * 256 + col0 + tx * 4) = v;
            }
        }
    } else {
        int c = col0 - 256 + tx * 4;
        float4 b4 = *(const float4*)(g_bias + c);
        #pragma unroll
        for (int i = 0; i < 4; i++) {
            int row = row0 + ty * 4 + i;
            if (row < M) {
                float4 v = make_float4(accr[i][0] + b4.x, accr[i][1] + b4.y,
                                       accr[i][2] + b4.z, accr[i][3] + b4.w);
                *(float4*)(acc + (size_t)row * 128 + c) = v;
            }
        }
    }
}

// ------------------------- per-node attention logits + denom zero ---------
__global__ void prep_attn(const float* __restrict__ att_s, const float* __restrict__ att_d, int n)
{
    int warp = (blockIdx.x * blockDim.x + threadIdx.x) >> 5;
    int lane = threadIdx.x & 31;
    if (warp >= n) return;
    float4 xs = *(const float4*)(g_xsxd + (size_t)warp * 256 + lane * 4);
    float4 xd = *(const float4*)(g_xsxd + (size_t)warp * 256 + 128 + lane * 4);
    float4 a4 = *(const float4*)(att_s + lane * 4);   // [h*32+c] layout matches lane*4
    float4 b4 = *(const float4*)(att_d + lane * 4);
    float s = xs.x * a4.x + xs.y * a4.y + xs.z * a4.z + xs.w * a4.w;
    float d = xd.x * b4.x + xd.y * b4.y + xd.z * b4.z + xd.w * b4.w;
    #pragma unroll
    for (int m = 1; m <= 4; m <<= 1) {
        s += __shfl_xor_sync(0xFFFFFFFFu, s, m);
        d += __shfl_xor_sync(0xFFFFFFFFu, d, m);
    }
    if ((lane & 7) == 0) {
        int h = lane >> 3;
        g_as[warp * 4 + h] = s;
        g_ad[warp * 4 + h] = d;
        g_denom[warp * 4 + h] = 0.f;
    }
}

// ------------------------- edge pass 1: w = exp(lrelu(e)), denom += w -----
__device__ __forceinline__ float lrelu_exp(float v) {
    v = v > 0.f ? v : LRELU * v;
    return __expf(v);
}

__global__ void edge_pass1(const int* __restrict__ src, const int* __restrict__ dst, int E)
{
    int e = blockIdx.x * blockDim.x + threadIdx.x;
    if (e >= E) return;
    int s = src[e], d = dst[e];
    float4 a = *(const float4*)(g_as + (size_t)s * 4);
    float4 b = *(const float4*)(g_ad + (size_t)d * 4);
    float4 w;
    w.x = lrelu_exp(a.x + b.x);
    w.y = lrelu_exp(a.y + b.y);
    w.z = lrelu_exp(a.z + b.z);
    w.w = lrelu_exp(a.w + b.w);
    *(float4*)(g_w + (size_t)e * 4) = w;
    float* dn = g_denom + (size_t)d * 4;
    atomicAdd(dn + 0, w.x);
    atomicAdd(dn + 1, w.y);
    atomicAdd(dn + 2, w.z);
    atomicAdd(dn + 3, w.w);
}

// ------------------------- edge pass 2: acc[dst] += xs[src] * alpha -------
__global__ __launch_bounds__(256) void edge_pass2(const int* __restrict__ src,
                                                  const int* __restrict__ dst,
                                                  float* __restrict__ acc, int E)
{
    int gw = (blockIdx.x * blockDim.x + threadIdx.x) >> 5;
    int lane = threadIdx.x & 31;
    if (gw >= E) return;
    int s = src[gw], d = dst[gw];
    int h = lane >> 3;
    float wv = g_w[(size_t)gw * 4 + h];
    float dn = g_denom[(size_t)d * 4 + h];
    float alpha = __fdividef(wv, dn + 1e-16f);
    float4 v = *(const float4*)(g_xsxd + (size_t)s * 256 + lane * 4);
    float* p = acc + (size_t)d * 128 + lane * 4;
    atomicAdd(p + 0, v.x * alpha);
    atomicAdd(p + 1, v.y * alpha);
    atomicAdd(p + 2, v.z * alpha);
    atomicAdd(p + 3, v.w * alpha);
}

// ------------------------- LayerNorm + ReLU -------------------------------
__global__ void ln_relu(const float* __restrict__ gamma, const float* __restrict__ beta, int n)
{
    int warp = (blockIdx.x * blockDim.x + threadIdx.x) >> 5;
    int lane = threadIdx.x & 31;
    if (warp >= n) return;
    float4 v = *(const float4*)(g_acc1 + (size_t)warp * 128 + lane * 4);
    float sum = v.x + v.y + v.z + v.w;
    float sq  = v.x * v.x + v.y * v.y + v.z * v.z + v.w * v.w;
    #pragma unroll
    for (int m = 1; m <= 16; m <<= 1) {
        sum += __shfl_xor_sync(0xFFFFFFFFu, sum, m);
        sq  += __shfl_xor_sync(0xFFFFFFFFu, sq, m);
    }
    float mean = sum * (1.f / 128.f);
    float var  = sq * (1.f / 128.f) - mean * mean;
    float rstd = rsqrtf(var + LN_EPS);
    float4 g4 = *(const float4*)(gamma + lane * 4);
    float4 b4 = *(const float4*)(beta + lane * 4);
    float4 o;
    o.x = fmaxf(0.f, (v.x - mean) * rstd * g4.x + b4.x);
    o.y = fmaxf(0.f, (v.y - mean) * rstd * g4.y + b4.y);
    o.z = fmaxf(0.f, (v.z - mean) * rstd * g4.z + b4.z);
    o.w = fmaxf(0.f, (v.w - mean) * rstd * g4.w + b4.w);
    *(float4*)(g_h + (size_t)warp * 128 + lane * 4) = o;
}

// ------------------------- driver ----------------------------------------
extern "C" void kernel_launch(void* const* d_in, const int* in_sizes, int n_in,
                              void* d_out, int out_size)
{
    const float* x        = (const float*)d_in[0];
    const int*   ei       = (const int*)  d_in[1];
    const float* W1_src   = (const float*)d_in[2];
    const float* W1_dst   = (const float*)d_in[3];
    const float* att1_src = (const float*)d_in[4];
    const float* att1_dst = (const float*)d_in[5];
    const float* b1       = (const float*)d_in[6];
    const float* Wl1      = (const float*)d_in[7];
    const float* bl1      = (const float*)d_in[8];
    const float* gamma    = (const float*)d_in[9];
    const float* beta     = (const float*)d_in[10];
    const float* W2_src   = (const float*)d_in[11];
    const float* W2_dst   = (const float*)d_in[12];
    const float* att2_src = (const float*)d_in[13];
    const float* att2_dst = (const float*)d_in[14];
    const float* b2       = (const float*)d_in[15];
    const float* Wl2      = (const float*)d_in[16];
    const float* bl2      = (const float*)d_in[17];
    float* out = (float*)d_out;

    const int n = NN;
    const int E = EE;
    const int* src = ei;
    const int* dst = ei + E;

    // device-symbol addresses usable from host launches only via kernels that
    // reference the globals directly; acc pointers passed explicitly.
    float* acc1;
    cudaGetSymbolAddress((void**)&acc1, g_acc1);
    float* hbuf;
    cudaGetSymbolAddress((void**)&hbuf, g_h);

    dim3 gemm_grid((n + TM - 1) / TM, NCAT / TN);
    int prep_blocks = (n * 32 + 255) / 256;
    int e1_blocks   = (E + 255) / 256;
    int e2_blocks   = (E * 32 + 255) / 256;

    // ----- layer 1 -----
    pack_w<<<64, 256>>>(W1_src, W1_dst, Wl1, bl1, b1);
    sgemm_pack<<<gemm_grid, 256>>>(x, acc1, n);
    prep_attn<<<prep_blocks, 256>>>(att1_src, att1_dst, n);
    edge_pass1<<<e1_blocks, 256>>>(src, dst, E);
    edge_pass2<<<e2_blocks, 256>>>(src, dst, acc1, E);
    ln_relu<<<prep_blocks, 256>>>(gamma, beta, n);

    // ----- layer 2 -----
    pack_w<<<64, 256>>>(W2_src, W2_dst, Wl2, bl2, b2);
    sgemm_pack<<<gemm_grid, 256>>>(hbuf, out, n);
    prep_attn<<<prep_blocks, 256>>>(att2_src, att2_dst, n);
    edge_pass1<<<e1_blocks, 256>>>(src, dst, E);
    edge_pass2<<<e2_blocks, 256>>>(src, dst, out, E);
}

// round 2
// speedup vs baseline: 1.0017x; 1.0017x over previous
#include <cuda_runtime.h>
#include <cuda_bf16.h>
#include <cstdint>

#define NN 50000
#define EE 800000
#define FDIM 128
#define HID 128
#define NCAT 384   // [W_src | W_dst | W_lin]
#define NHEAD 4
#define LRELU 0.2f
#define LN_EPS 1e-5f

// ------------------------- scratch (device globals; no allocs allowed) -----
__device__ float g_xsxd[(size_t)NN * 256];   // per row: [xs(128) | xd(128)]
__device__ float g_acc1[(size_t)NN * 128];   // layer1 accumulator (lin+bias, then +gat)
__device__ float g_h[(size_t)NN * 128];      // layer1 output after LN+ReLU
__device__ float g_w[(size_t)EE * NHEAD];    // per-edge exp weights
__device__ float g_as[NN * NHEAD];
__device__ float g_ad[NN * NHEAD];
__device__ float g_denom[NN * NHEAD];
__device__ float g_Wcat[FDIM * NCAT];        // packed weights [K=128, 384]
__device__ float g_bias[128];                // bl + b_gat

// ------------------------- weight packing --------------------------------
__global__ void pack_w(const float* __restrict__ Wsrc, const float* __restrict__ Wdst,
                       const float* __restrict__ Wl, const float* __restrict__ bl,
                       const float* __restrict__ bg)
{
    int i = blockIdx.x * blockDim.x + threadIdx.x;
    if (i < 128 * 128) {
        int k = i >> 7, c = i & 127;
        g_Wcat[k * NCAT + c]       = Wsrc[i];
        g_Wcat[k * NCAT + 128 + c] = Wdst[i];
        g_Wcat[k * NCAT + 256 + c] = Wl[i];
    }
    if (i < 128) g_bias[i] = bl[i] + bg[i];
}

// ------------------------- fused SGEMM: A[M,128] @ Wcat[128,384] ----------
// cols [0,256) -> g_xsxd (stride 256); cols [256,384) -> acc (stride 128, +bias)
#define TM 64
#define TN 64
#define KC 32

__global__ __launch_bounds__(256) void sgemm_pack(const float* __restrict__ A,
                                                  float* __restrict__ acc, int M)
{
    __shared__ float As[KC][TM + 4];
    __shared__ float Bs[KC][TN + 4];
    const int row0 = blockIdx.x * TM;
    const int col0 = blockIdx.y * TN;
    const int tid = threadIdx.x;
    const int tx = tid & 15, ty = tid >> 4;

    float accr[4][4] = {};

    for (int k0 = 0; k0 < 128; k0 += KC) {
        // load A tile 64x32 (transposed into smem)
        {
            int r  = tid >> 3;           // 0..31
            int kv = (tid & 7) * 4;      // 0..28
            #pragma unroll
            for (int rr = 0; rr < 2; rr++) {
                int row = row0 + r + rr * 32;
                float4 v = make_float4(0.f, 0.f, 0.f, 0.f);
                if (row < M) v = *(const float4*)(A + (size_t)row * 128 + k0 + kv);
                As[kv + 0][r + rr * 32] = v.x;
                As[kv + 1][r + rr * 32] = v.y;
                As[kv + 2][r + rr * 32] = v.z;
                As[kv + 3][r + rr * 32] = v.w;
            }
        }
        // load B tile 32x64
        {
            int k  = tid >> 4;           // 0..15
            int cv = (tid & 15) * 4;
            #pragma unroll
            for (int kk2 = 0; kk2 < 2; kk2++) {
                float4 v = *(const float4*)(g_Wcat + (size_t)(k0 + k + kk2 * 16) * NCAT + col0 + cv);
                *(float4*)&Bs[k + kk2 * 16][cv] = v;
            }
        }
        __syncthreads();
        #pragma unroll
        for (int kk = 0; kk < KC; kk++) {
            float a[4], b[4];
            *(float4*)a = *(const float4*)&As[kk][ty * 4];
            *(float4*)b = *(const float4*)&Bs[kk][tx * 4];
            #pragma unroll
            for (int i = 0; i < 4; i++)
                #pragma unroll
                for (int j = 0; j < 4; j++)
                    accr[i][j] = fmaf(a[i], b[j], accr[i][j]);
        }
        __syncthreads();
    }

    if (col0 < 256) {
        #pragma unroll
        for (int i = 0; i < 4; i++) {
            int row = row0 + ty * 4 + i;
            if (row < M) {
                float4 v = make_float4(accr[i][0], accr[i][1], accr[i][2], accr[i][3]);
                *(float4*)(g_xsxd + (size_t)row * 256 + col0 + tx * 4) = v;
            }
        }
    } else {
        int c = col0 - 256 + tx * 4;
        float4 b4 = *(const float4*)(g_bias + c);
        #pragma unroll
        for (int i = 0; i < 4; i++) {
            int row = row0 + ty * 4 + i;
            if (row < M) {
                float4 v = make_float4(accr[i][0] + b4.x, accr[i][1] + b4.y,
                                       accr[i][2] + b4.z, accr[i][3] + b4.w);
                *(float4*)(acc + (size_t)row * 128 + c) = v;
            }
        }
    }
}

// ------------------------- per-node attention logits + denom zero ---------
__global__ void prep_attn(const float* __restrict__ att_s, const float* __restrict__ att_d, int n)
{
    int warp = (blockIdx.x * blockDim.x + threadIdx.x) >> 5;
    int lane = threadIdx.x & 31;
    if (warp >= n) return;
    float4 xs = *(const float4*)(g_xsxd + (size_t)warp * 256 + lane * 4);
    float4 xd = *(const float4*)(g_xsxd + (size_t)warp * 256 + 128 + lane * 4);
    float4 a4 = *(const float4*)(att_s + lane * 4);   // [h*32+c] layout matches lane*4
    float4 b4 = *(const float4*)(att_d + lane * 4);
    float s = xs.x * a4.x + xs.y * a4.y + xs.z * a4.z + xs.w * a4.w;
    float d = xd.x * b4.x + xd.y * b4.y + xd.z * b4.z + xd.w * b4.w;
    #pragma unroll
    for (int m = 1; m <= 4; m <<= 1) {
        s += __shfl_xor_sync(0xFFFFFFFFu, s, m);
        d += __shfl_xor_sync(0xFFFFFFFFu, d, m);
    }
    if ((lane & 7) == 0) {
        int h = lane >> 3;
        g_as[warp * 4 + h] = s;
        g_ad[warp * 4 + h] = d;
        g_denom[warp * 4 + h] = 0.f;
    }
}

// ------------------------- edge pass 1: w = exp(lrelu(e)), denom += w -----
__device__ __forceinline__ float lrelu_exp(float v) {
    v = v > 0.f ? v : LRELU * v;
    return __expf(v);
}

__global__ void edge_pass1(const int* __restrict__ src, const int* __restrict__ dst, int E)
{
    int e = blockIdx.x * blockDim.x + threadIdx.x;
    if (e >= E) return;
    int s = src[e], d = dst[e];
    float4 a = *(const float4*)(g_as + (size_t)s * 4);
    float4 b = *(const float4*)(g_ad + (size_t)d * 4);
    float4 w;
    w.x = lrelu_exp(a.x + b.x);
    w.y = lrelu_exp(a.y + b.y);
    w.z = lrelu_exp(a.z + b.z);
    w.w = lrelu_exp(a.w + b.w);
    *(float4*)(g_w + (size_t)e * 4) = w;
    float* dn = g_denom + (size_t)d * 4;
    atomicAdd(dn + 0, w.x);
    atomicAdd(dn + 1, w.y);
    atomicAdd(dn + 2, w.z);
    atomicAdd(dn + 3, w.w);
}

// ------------------------- edge pass 2: acc[dst] += xs[src] * alpha -------
__global__ __launch_bounds__(256) void edge_pass2(const int* __restrict__ src,
                                                  const int* __restrict__ dst,
                                                  float* __restrict__ acc, int E)
{
    int gw = (blockIdx.x * blockDim.x + threadIdx.x) >> 5;
    int lane = threadIdx.x & 31;
    if (gw >= E) return;
    int s = src[gw], d = dst[gw];
    int h = lane >> 3;
    float wv = g_w[(size_t)gw * 4 + h];
    float dn = g_denom[(size_t)d * 4 + h];
    float alpha = __fdividef(wv, dn + 1e-16f);
    float4 v = *(const float4*)(g_xsxd + (size_t)s * 256 + lane * 4);
    float* p = acc + (size_t)d * 128 + lane * 4;
    atomicAdd(p + 0, v.x * alpha);
    atomicAdd(p + 1, v.y * alpha);
    atomicAdd(p + 2, v.z * alpha);
    atomicAdd(p + 3, v.w * alpha);
}

// ------------------------- LayerNorm + ReLU -------------------------------
__global__ void ln_relu(const float* __restrict__ gamma, const float* __restrict__ beta, int n)
{
    int warp = (blockIdx.x * blockDim.x + threadIdx.x) >> 5;
    int lane = threadIdx.x & 31;
    if (warp >= n) return;
    float4 v = *(const float4*)(g_acc1 + (size_t)warp * 128 + lane * 4);
    float sum = v.x + v.y + v.z + v.w;
    float sq  = v.x * v.x + v.y * v.y + v.z * v.z + v.w * v.w;
    #pragma unroll
    for (int m = 1; m <= 16; m <<= 1) {
        sum += __shfl_xor_sync(0xFFFFFFFFu, sum, m);
        sq  += __shfl_xor_sync(0xFFFFFFFFu, sq, m);
    }
    float mean = sum * (1.f / 128.f);
    float var  = sq * (1.f / 128.f) - mean * mean;
    float rstd = rsqrtf(var + LN_EPS);
    float4 g4 = *(const float4*)(gamma + lane * 4);
    float4 b4 = *(const float4*)(beta + lane * 4);
    float4 o;
    o.x = fmaxf(0.f, (v.x - mean) * rstd * g4.x + b4.x);
    o.y = fmaxf(0.f, (v.y - mean) * rstd * g4.y + b4.y);
    o.z = fmaxf(0.f, (v.z - mean) * rstd * g4.z + b4.z);
    o.w = fmaxf(0.f, (v.w - mean) * rstd * g4.w + b4.w);
    *(float4*)(g_h + (size_t)warp * 128 + lane * 4) = o;
}

// ------------------------- driver ----------------------------------------
extern "C" void kernel_launch(void* const* d_in, const int* in_sizes, int n_in,
                              void* d_out, int out_size)
{
    const float* x        = (const float*)d_in[0];
    const int*   ei       = (const int*)  d_in[1];
    const float* W1_src   = (const float*)d_in[2];
    const float* W1_dst   = (const float*)d_in[3];
    const float* att1_src = (const float*)d_in[4];
    const float* att1_dst = (const float*)d_in[5];
    const float* b1       = (const float*)d_in[6];
    const float* Wl1      = (const float*)d_in[7];
    const float* bl1      = (const float*)d_in[8];
    const float* gamma    = (const float*)d_in[9];
    const float* beta     = (const float*)d_in[10];
    const float* W2_src   = (const float*)d_in[11];
    const float* W2_dst   = (const float*)d_in[12];
    const float* att2_src = (const float*)d_in[13];
    const float* att2_dst = (const float*)d_in[14];
    const float* b2       = (const float*)d_in[15];
    const float* Wl2      = (const float*)d_in[16];
    const float* bl2      = (const float*)d_in[17];
    float* out = (float*)d_out;

    const int n = NN;
    const int E = EE;
    const int* src = ei;
    const int* dst = ei + E;

    // device-symbol addresses usable from host launches only via kernels that
    // reference the globals directly; acc pointers passed explicitly.
    float* acc1;
    cudaGetSymbolAddress((void**)&acc1, g_acc1);
    float* hbuf;
    cudaGetSymbolAddress((void**)&hbuf, g_h);

    dim3 gemm_grid((n + TM - 1) / TM, NCAT / TN);
    int prep_blocks = (n * 32 + 255) / 256;
    int e1_blocks   = (E + 255) / 256;
    int e2_blocks   = (E * 32 + 255) / 256;

    // ----- layer 1 -----
    pack_w<<<64, 256>>>(W1_src, W1_dst, Wl1, bl1, b1);
    sgemm_pack<<<gemm_grid, 256>>>(x, acc1, n);
    prep_attn<<<prep_blocks, 256>>>(att1_src, att1_dst, n);
    edge_pass1<<<e1_blocks, 256>>>(src, dst, E);
    edge_pass2<<<e2_blocks, 256>>>(src, dst, acc1, E);
    ln_relu<<<prep_blocks, 256>>>(gamma, beta, n);

    // ----- layer 2 -----
    pack_w<<<64, 256>>>(W2_src, W2_dst, Wl2, bl2, b2);
    sgemm_pack<<<gemm_grid, 256>>>(hbuf, out, n);
    prep_attn<<<prep_blocks, 256>>>(att2_src, att2_dst, n);
    edge_pass1<<<e1_blocks, 256>>>(src, dst, E);
    edge_pass2<<<e2_blocks, 256>>>(src, dst, out, E);
}

// round 3
// speedup vs baseline: 2.1708x; 2.1670x over previous
#include <cuda_runtime.h>
#include <cuda_bf16.h>
#include <cstdint>

#define NN 50000
#define EE 800000
#define NCAT 384
#define NHEAD 4
#define LRELU 0.2f
#define LN_EPS 1e-5f

// ------------------------- scratch (device globals) ----------------------
__device__ float g_xsxd[(size_t)NN * 256];   // per row: [xs(128) | xd(128)]
__device__ float g_acc1[(size_t)NN * 128];
__device__ float g_h[(size_t)NN * 128];
__device__ float g_w[(size_t)EE * NHEAD];    // per-edge exp weights (CSR order)
__device__ float g_as[NN * NHEAD];
__device__ float g_ad[NN * NHEAD];
__device__ float g_denom[NN * NHEAD];
__device__ float g_Wcat[128 * NCAT];
__device__ float g_bias[128];
// CSR
__device__ int g_cnt[NN];
__device__ int g_rowptr[NN + 1];
__device__ int g_woff[NN];
__device__ int g_csrc[EE];

// ------------------------- weight packing --------------------------------
__global__ void pack_w(const float* __restrict__ Wsrc, const float* __restrict__ Wdst,
                       const float* __restrict__ Wl, const float* __restrict__ bl,
                       const float* __restrict__ bg)
{
    int i = blockIdx.x * blockDim.x + threadIdx.x;
    if (i < 128 * 128) {
        int k = i >> 7, c = i & 127;
        g_Wcat[k * NCAT + c]       = Wsrc[i];
        g_Wcat[k * NCAT + 128 + c] = Wdst[i];
        g_Wcat[k * NCAT + 256 + c] = Wl[i];
    }
    if (i < 128) g_bias[i] = bl[i] + bg[i];
}

// ------------------------- CSR build -------------------------------------
__global__ void hist_k(const int* __restrict__ dst, int E)
{
    int e = blockIdx.x * blockDim.x + threadIdx.x;
    if (e < E) atomicAdd(&g_cnt[dst[e]], 1);
}

__global__ void scan_k(int E)
{
    __shared__ int ssum[1024];
    const int t = threadIdx.x;
    const int CH = (NN + 1023) / 1024;  // 49
    int base = t * CH;
    int s = 0;
    for (int i = 0; i < CH; i++) {
        int idx = base + i;
        if (idx < NN) s += g_cnt[idx];
    }
    ssum[t] = s;
    __syncthreads();
    for (int off = 1; off < 1024; off <<= 1) {
        int v = (t >= off) ? ssum[t - off] : 0;
        __syncthreads();
        ssum[t] += v;
        __syncthreads();
    }
    int run = ssum[t] - s;  // exclusive start of this chunk
    for (int i = 0; i < CH; i++) {
        int idx = base + i;
        if (idx < NN) {
            g_rowptr[idx] = run;
            g_woff[idx] = run;
            run += g_cnt[idx];
        }
    }
    if (t == 1023) g_rowptr[NN] = E;
}

__global__ void scatter_k(const int* __restrict__ src, const int* __restrict__ dst, int E)
{
    int e = blockIdx.x * blockDim.x + threadIdx.x;
    if (e >= E) return;
    int d = dst[e];
    int p = atomicAdd(&g_woff[d], 1);
    g_csrc[p] = src[e];
}

// ------------------------- tf32 tensor-core GEMM -------------------------
// C[M,384] = A[M,128] @ g_Wcat[128,384]; cols [0,128)->xs, [128,256)->xd,
// [256,384)->acc (+bias). BM=128, BN=128, 256 threads, warp tile 64x32.
__device__ __forceinline__ uint32_t f2tf32(float f)
{
    uint32_t u;
    asm("cvt.rna.tf32.f32 %0, %1;" : "=r"(u) : "f"(f));
    return u;
}

__global__ __launch_bounds__(256) void gemm_tf32(const float* __restrict__ A,
                                                 float* __restrict__ acc, int M)
{
    __shared__ uint32_t As[128][40];   // k-chunk 32, padded (bank: 8m+k unique)
    __shared__ uint32_t Bs[32][136];   // padded (bank: 8k+col unique)

    const int tid = threadIdx.x;
    const int lane = tid & 31;
    const int warp = tid >> 5;
    const int wm = warp >> 2;          // 0..1
    const int wn = warp & 3;           // 0..3
    const int row0 = blockIdx.x * 128;
    const int col0 = blockIdx.y * 128;

    float c[4][4][4];
    #pragma unroll
    for (int i = 0; i < 4; i++)
        #pragma unroll
        for (int j = 0; j < 4; j++)
            #pragma unroll
            for (int q = 0; q < 4; q++) c[i][j][q] = 0.f;

    for (int k0 = 0; k0 < 128; k0 += 32) {
        // A tile 128x32
        {
            int ar = tid >> 1;
            int ac = (tid & 1) * 16;
            int grow = row0 + ar;
            #pragma unroll
            for (int j = 0; j < 4; j++) {
                float4 v = make_float4(0.f, 0.f, 0.f, 0.f);
                if (grow < M) v = *(const float4*)(A + (size_t)grow * 128 + k0 + ac + j * 4);
                uint32_t* p = &As[ar][ac + j * 4];
                p[0] = f2tf32(v.x); p[1] = f2tf32(v.y);
                p[2] = f2tf32(v.z); p[3] = f2tf32(v.w);
            }
        }
        // B tile 32x128
        {
            int br = tid >> 3;
            int bc = (tid & 7) * 16;
            #pragma unroll
            for (int j = 0; j < 4; j++) {
                float4 v = *(const float4*)(g_Wcat + (size_t)(k0 + br) * NCAT + col0 + bc + j * 4);
                uint32_t* p = &Bs[br][bc + j * 4];
                p[0] = f2tf32(v.x); p[1] = f2tf32(v.y);
                p[2] = f2tf32(v.z); p[3] = f2tf32(v.w);
            }
        }
        __syncthreads();

        #pragma unroll
        for (int kk = 0; kk < 4; kk++) {
            const int kb = kk * 8 + (lane & 3);
            uint32_t af[4][4], bf[4][2];
            #pragma unroll
            for (int mt = 0; mt < 4; mt++) {
                int r = wm * 64 + mt * 16 + (lane >> 2);
                af[mt][0] = As[r][kb];
                af[mt][1] = As[r + 8][kb];
                af[mt][2] = As[r][kb + 4];
                af[mt][3] = As[r + 8][kb + 4];
            }
            #pragma unroll
            for (int nt = 0; nt < 4; nt++) {
                int cc = wn * 32 + nt * 8 + (lane >> 2);
                bf[nt][0] = Bs[kk * 8 + (lane & 3)][cc];
                bf[nt][1] = Bs[kk * 8 + (lane & 3) + 4][cc];
            }
            #pragma unroll
            for (int mt = 0; mt < 4; mt++)
                #pragma unroll
                for (int nt = 0; nt < 4; nt++) {
                    asm volatile(
                        "mma.sync.aligned.m16n8k8.row.col.f32.tf32.tf32.f32 "
                        "{%0,%1,%2,%3}, {%4,%5,%6,%7}, {%8,%9}, {%0,%1,%2,%3};"
                        : "+f"(c[mt][nt][0]), "+f"(c[mt][nt][1]),
                          "+f"(c[mt][nt][2]), "+f"(c[mt][nt][3])
                        : "r"(af[mt][0]), "r"(af[mt][1]), "r"(af[mt][2]), "r"(af[mt][3]),
                          "r"(bf[nt][0]), "r"(bf[nt][1]));
                }
        }
        __syncthreads();
    }

    // epilogue
    const int y = blockIdx.y;
    #pragma unroll
    for (int mt = 0; mt < 4; mt++) {
        #pragma unroll
        for (int nt = 0; nt < 4; nt++) {
            int r = row0 + wm * 64 + mt * 16 + (lane >> 2);
            int cc = wn * 32 + nt * 8 + (lane & 3) * 2;
            float2 v01 = make_float2(c[mt][nt][0], c[mt][nt][1]);
            float2 v23 = make_float2(c[mt][nt][2], c[mt][nt][3]);
            if (y == 0) {
                if (r < M)     *(float2*)(g_xsxd + (size_t)r * 256 + cc) = v01;
                if (r + 8 < M) *(float2*)(g_xsxd + (size_t)(r + 8) * 256 + cc) = v23;
            } else if (y == 1) {
                if (r < M)     *(float2*)(g_xsxd + (size_t)r * 256 + 128 + cc) = v01;
                if (r + 8 < M) *(float2*)(g_xsxd + (size_t)(r + 8) * 256 + 128 + cc) = v23;
            } else {
                float2 b2 = *(const float2*)(g_bias + cc);
                v01.x += b2.x; v01.y += b2.y;
                v23.x += b2.x; v23.y += b2.y;
                if (r < M)     *(float2*)(acc + (size_t)r * 128 + cc) = v01;
                if (r + 8 < M) *(float2*)(acc + (size_t)(r + 8) * 128 + cc) = v23;
            }
        }
    }
}

// ------------------------- per-node attention logits ----------------------
__global__ void prep_attn(const float* __restrict__ att_s, const float* __restrict__ att_d, int n)
{
    int node = (blockIdx.x * blockDim.x + threadIdx.x) >> 5;
    int lane = threadIdx.x & 31;
    if (node >= n) return;
    float4 xs = *(const float4*)(g_xsxd + (size_t)node * 256 + lane * 4);
    float4 xd = *(const float4*)(g_xsxd + (size_t)node * 256 + 128 + lane * 4);
    float4 a4 = *(const float4*)(att_s + lane * 4);
    float4 b4 = *(const float4*)(att_d + lane * 4);
    float s = xs.x * a4.x + xs.y * a4.y + xs.z * a4.z + xs.w * a4.w;
    float d = xd.x * b4.x + xd.y * b4.y + xd.z * b4.z + xd.w * b4.w;
    #pragma unroll
    for (int m = 1; m <= 4; m <<= 1) {
        s += __shfl_xor_sync(0xFFFFFFFFu, s, m);
        d += __shfl_xor_sync(0xFFFFFFFFu, d, m);
    }
    if ((lane & 7) == 0) {
        int h = lane >> 3;
        g_as[node * 4 + h] = s;
        g_ad[node * 4 + h] = d;
    }
}

// ------------------------- pass1 (gather): w + denom, no atomics ----------
__device__ __forceinline__ float lrelu_exp(float v)
{
    v = v > 0.f ? v : LRELU * v;
    return __expf(v);
}

__global__ __launch_bounds__(256) void pass1_gather(int n)
{
    int node = (blockIdx.x * blockDim.x + threadIdx.x) >> 5;
    int lane = threadIdx.x & 31;
    if (node >= n) return;
    int rs = g_rowptr[node], re = g_rowptr[node + 1];
    float4 ad = *(const float4*)(g_ad + (size_t)node * 4);  // broadcast
    float4 dsum = make_float4(0.f, 0.f, 0.f, 0.f);
    for (int e = rs + lane; e < re; e += 32) {
        int s = g_csrc[e];
        float4 a = *(const float4*)(g_as + (size_t)s * 4);
        float4 w;
        w.x = lrelu_exp(a.x + ad.x);
        w.y = lrelu_exp(a.y + ad.y);
        w.z = lrelu_exp(a.z + ad.z);
        w.w = lrelu_exp(a.w + ad.w);
        *(float4*)(g_w + (size_t)e * 4) = w;
        dsum.x += w.x; dsum.y += w.y; dsum.z += w.z; dsum.w += w.w;
    }
    #pragma unroll
    for (int m = 16; m >= 1; m >>= 1) {
        dsum.x += __shfl_xor_sync(0xFFFFFFFFu, dsum.x, m);
        dsum.y += __shfl_xor_sync(0xFFFFFFFFu, dsum.y, m);
        dsum.z += __shfl_xor_sync(0xFFFFFFFFu, dsum.z, m);
        dsum.w += __shfl_xor_sync(0xFFFFFFFFu, dsum.w, m);
    }
    if (lane == 0) *(float4*)(g_denom + (size_t)node * 4) = dsum;
}

// ------------------------- pass2 (gather SpMM): acc += sum alpha*xs -------
__global__ __launch_bounds__(256) void pass2_gather(float* __restrict__ acc, int n)
{
    int node = (blockIdx.x * blockDim.x + threadIdx.x) >> 5;
    int lane = threadIdx.x & 31;
    if (node >= n) return;
    int h = lane >> 3;
    int rs = g_rowptr[node], re = g_rowptr[node + 1];
    float inv = __fdividef(1.f, g_denom[(size_t)node * 4 + h] + 1e-16f);
    float4 a = make_float4(0.f, 0.f, 0.f, 0.f);
    int e = rs;
    #pragma unroll 2
    for (; e < re; e++) {
        int s = g_csrc[e];                       // broadcast load
        float w = g_w[(size_t)e * 4 + h] * inv;
        float4 xv = *(const float4*)(g_xsxd + (size_t)s * 256 + lane * 4);
        a.x = fmaf(w, xv.x, a.x);
        a.y = fmaf(w, xv.y, a.y);
        a.z = fmaf(w, xv.z, a.z);
        a.w = fmaf(w, xv.w, a.w);
    }
    float4 o = *(const float4*)(acc + (size_t)node * 128 + lane * 4);
    o.x += a.x; o.y += a.y; o.z += a.z; o.w += a.w;
    *(float4*)(acc + (size_t)node * 128 + lane * 4) = o;
}

// ------------------------- LayerNorm + ReLU -------------------------------
__global__ void ln_relu(const float* __restrict__ gamma, const float* __restrict__ beta, int n)
{
    int node = (blockIdx.x * blockDim.x + threadIdx.x) >> 5;
    int lane = threadIdx.x & 31;
    if (node >= n) return;
    float4 v = *(const float4*)(g_acc1 + (size_t)node * 128 + lane * 4);
    float sum = v.x + v.y + v.z + v.w;
    float sq  = v.x * v.x + v.y * v.y + v.z * v.z + v.w * v.w;
    #pragma unroll
    for (int m = 1; m <= 16; m <<= 1) {
        sum += __shfl_xor_sync(0xFFFFFFFFu, sum, m);
        sq  += __shfl_xor_sync(0xFFFFFFFFu, sq, m);
    }
    float mean = sum * (1.f / 128.f);
    float var  = sq * (1.f / 128.f) - mean * mean;
    float rstd = rsqrtf(var + LN_EPS);
    float4 g4 = *(const float4*)(gamma + lane * 4);
    float4 b4 = *(const float4*)(beta + lane * 4);
    float4 o;
    o.x = fmaxf(0.f, (v.x - mean) * rstd * g4.x + b4.x);
    o.y = fmaxf(0.f, (v.y - mean) * rstd * g4.y + b4.y);
    o.z = fmaxf(0.f, (v.z - mean) * rstd * g4.z + b4.z);
    o.w = fmaxf(0.f, (v.w - mean) * rstd * g4.w + b4.w);
    *(float4*)(g_h + (size_t)node * 128 + lane * 4) = o;
}

// ------------------------- driver ----------------------------------------
extern "C" void kernel_launch(void* const* d_in, const int* in_sizes, int n_in,
                              void* d_out, int out_size)
{
    const float* x        = (const float*)d_in[0];
    const int*   ei       = (const int*)  d_in[1];
    const float* W1_src   = (const float*)d_in[2];
    const float* W1_dst   = (const float*)d_in[3];
    const float* att1_src = (const float*)d_in[4];
    const float* att1_dst = (const float*)d_in[5];
    const float* b1       = (const float*)d_in[6];
    const float* Wl1      = (const float*)d_in[7];
    const float* bl1      = (const float*)d_in[8];
    const float* gamma    = (const float*)d_in[9];
    const float* beta     = (const float*)d_in[10];
    const float* W2_src   = (const float*)d_in[11];
    const float* W2_dst   = (const float*)d_in[12];
    const float* att2_src = (const float*)d_in[13];
    const float* att2_dst = (const float*)d_in[14];
    const float* b2       = (const float*)d_in[15];
    const float* Wl2      = (const float*)d_in[16];
    const float* bl2      = (const float*)d_in[17];
    float* out = (float*)d_out;

    const int n = NN;
    const int E = EE;
    const int* src = ei;
    const int* dst = ei + E;

    float *acc1, *hbuf;
    void* p;
    cudaGetSymbolAddress(&p, g_acc1); acc1 = (float*)p;
    cudaGetSymbolAddress(&p, g_h);    hbuf = (float*)p;
    void* cntp;
    cudaGetSymbolAddress(&cntp, g_cnt);

    dim3 gemm_grid((n + 127) / 128, 3);
    int node_blocks = (n * 32 + 255) / 256;
    int edge_blocks = (E + 255) / 256;

    // ----- CSR build (once, reused by both layers) -----
    cudaMemsetAsync(cntp, 0, NN * sizeof(int));
    hist_k<<<edge_blocks, 256>>>(dst, E);
    scan_k<<<1, 1024>>>(E);
    scatter_k<<<edge_blocks, 256>>>(src, dst, E);

    // ----- layer 1 -----
    pack_w<<<64, 256>>>(W1_src, W1_dst, Wl1, bl1, b1);
    gemm_tf32<<<gemm_grid, 256>>>(x, acc1, n);
    prep_attn<<<node_blocks, 256>>>(att1_src, att1_dst, n);
    pass1_gather<<<node_blocks, 256>>>(n);
    pass2_gather<<<node_blocks, 256>>>(acc1, n);
    ln_relu<<<node_blocks, 256>>>(gamma, beta, n);

    // ----- layer 2 -----
    pack_w<<<64, 256>>>(W2_src, W2_dst, Wl2, bl2, b2);
    gemm_tf32<<<gemm_grid, 256>>>(hbuf, out, n);
    prep_attn<<<node_blocks, 256>>>(att2_src, att2_dst, n);
    pass1_gather<<<node_blocks, 256>>>(n);
    pass2_gather<<<node_blocks, 256>>>(out, n);
}

// round 4
// speedup vs baseline: 2.5354x; 1.1679x over previous
#include <cuda_runtime.h>
#include <cuda_bf16.h>
#include <cuda_fp16.h>
#include <cstdint>

#define NN 50000
#define EE 800000
#define NCAT 384
#define LRELU 0.2f
#define LN_EPS 1e-5f

// ------------------------- scratch (device globals) ----------------------
__device__ __align__(16) __half g_xs_h[(size_t)NN * 128];  // fp16 xs
__device__ float g_h[(size_t)NN * 128];                    // layer1 output
__device__ float g_w[(size_t)EE * 4];                      // per-edge exp weights
__device__ float g_as[NN * 4];
__device__ float g_ad[NN * 4];
__device__ float g_Wcat[2 * 128 * NCAT];
__device__ float g_biasA[2 * 128];
__device__ float g_acc1[(size_t)NN * 128];
// CSR
__device__ int g_cnt[NN];
__device__ int g_rowptr[NN + 1];
__device__ int g_woff[NN];
__device__ int g_csrc[EE];

// ------------------------- weight packing (both layers) ------------------
__global__ void pack_all(const float* __restrict__ W1s, const float* __restrict__ W1d,
                         const float* __restrict__ Wl1, const float* __restrict__ bl1,
                         const float* __restrict__ b1,
                         const float* __restrict__ W2s, const float* __restrict__ W2d,
                         const float* __restrict__ Wl2, const float* __restrict__ bl2,
                         const float* __restrict__ b2)
{
    int i = blockIdx.x * blockDim.x + threadIdx.x;
    if (i < 128 * 128) {
        int k = i >> 7, c = i & 127;
        g_Wcat[k * NCAT + c]       = W1s[i];
        g_Wcat[k * NCAT + 128 + c] = W1d[i];
        g_Wcat[k * NCAT + 256 + c] = Wl1[i];
        float* W2 = g_Wcat + 128 * NCAT;
        W2[k * NCAT + c]       = W2s[i];
        W2[k * NCAT + 128 + c] = W2d[i];
        W2[k * NCAT + 256 + c] = Wl2[i];
    }
    if (i < 128) {
        g_biasA[i]       = bl1[i] + b1[i];
        g_biasA[128 + i] = bl2[i] + b2[i];
    }
}

// ------------------------- CSR build -------------------------------------
__global__ void hist_k(const int* __restrict__ dst, int E)
{
    int e = blockIdx.x * blockDim.x + threadIdx.x;
    if (e < E) atomicAdd(&g_cnt[dst[e]], 1);
}

__global__ void scan_k(int E)
{
    __shared__ int ssum[1024];
    const int t = threadIdx.x;
    const int CH = (NN + 1023) / 1024;
    int base = t * CH;
    int s = 0;
    for (int i = 0; i < CH; i++) {
        int idx = base + i;
        if (idx < NN) s += g_cnt[idx];
    }
    ssum[t] = s;
    __syncthreads();
    for (int off = 1; off < 1024; off <<= 1) {
        int v = (t >= off) ? ssum[t - off] : 0;
        __syncthreads();
        ssum[t] += v;
        __syncthreads();
    }
    int run = ssum[t] - s;
    for (int i = 0; i < CH; i++) {
        int idx = base + i;
        if (idx < NN) {
            g_rowptr[idx] = run;
            g_woff[idx] = run;
            run += g_cnt[idx];
        }
    }
    if (t == 1023) g_rowptr[NN] = E;
}

__global__ void scatter_k(const int* __restrict__ src, const int* __restrict__ dst, int E)
{
    int e = blockIdx.x * blockDim.x + threadIdx.x;
    if (e >= E) return;
    int d = dst[e];
    int p = atomicAdd(&g_woff[d], 1);
    g_csrc[p] = src[e];
}

// ------------------------- tf32 GEMM + fused attention epilogue ----------
// C[M,384] = A[M,128] @ Wcat[128,384].
// blockIdx.y==0: xs cols -> fp16 g_xs_h + a_s per-head dots -> g_as
// blockIdx.y==1: xd cols -> a_d dots only -> g_ad (xd never materialized)
// blockIdx.y==2: lin cols + bias -> acc
__device__ __forceinline__ uint32_t f2tf32(float f)
{
    uint32_t u;
    asm("cvt.rna.tf32.f32 %0, %1;" : "=r"(u) : "f"(f));
    return u;
}

__global__ __launch_bounds__(256) void gemm_tf32(const float* __restrict__ A,
                                                 float* __restrict__ acc,
                                                 const float* __restrict__ Wcat,
                                                 const float* __restrict__ biasv,
                                                 const float* __restrict__ att_s,
                                                 const float* __restrict__ att_d,
                                                 int M)
{
    __shared__ uint32_t As[128][40];
    __shared__ uint32_t Bs[32][136];

    const int tid = threadIdx.x;
    const int lane = tid & 31;
    const int warp = tid >> 5;
    const int wm = warp >> 2;
    const int wn = warp & 3;
    const int row0 = blockIdx.x * 128;
    const int y = blockIdx.y;
    const int col0 = y * 128;

    float c[4][4][4];
    #pragma unroll
    for (int i = 0; i < 4; i++)
        #pragma unroll
        for (int j = 0; j < 4; j++)
            #pragma unroll
            for (int q = 0; q < 4; q++) c[i][j][q] = 0.f;

    for (int k0 = 0; k0 < 128; k0 += 32) {
        {
            int ar = tid >> 1;
            int ac = (tid & 1) * 16;
            int grow = row0 + ar;
            #pragma unroll
            for (int j = 0; j < 4; j++) {
                float4 v = make_float4(0.f, 0.f, 0.f, 0.f);
                if (grow < M) v = *(const float4*)(A + (size_t)grow * 128 + k0 + ac + j * 4);
                uint32_t* p = &As[ar][ac + j * 4];
                p[0] = f2tf32(v.x); p[1] = f2tf32(v.y);
                p[2] = f2tf32(v.z); p[3] = f2tf32(v.w);
            }
        }
        {
            int br = tid >> 3;
            int bc = (tid & 7) * 16;
            #pragma unroll
            for (int j = 0; j < 4; j++) {
                float4 v = *(const float4*)(Wcat + (size_t)(k0 + br) * NCAT + col0 + bc + j * 4);
                uint32_t* p = &Bs[br][bc + j * 4];
                p[0] = f2tf32(v.x); p[1] = f2tf32(v.y);
                p[2] = f2tf32(v.z); p[3] = f2tf32(v.w);
            }
        }
        __syncthreads();

        #pragma unroll
        for (int kk = 0; kk < 4; kk++) {
            const int kb = kk * 8 + (lane & 3);
            uint32_t af[4][4], bf[4][2];
            #pragma unroll
            for (int mt = 0; mt < 4; mt++) {
                int r = wm * 64 + mt * 16 + (lane >> 2);
                af[mt][0] = As[r][kb];
                af[mt][1] = As[r + 8][kb];
                af[mt][2] = As[r][kb + 4];
                af[mt][3] = As[r + 8][kb + 4];
            }
            #pragma unroll
            for (int nt = 0; nt < 4; nt++) {
                int cc = wn * 32 + nt * 8 + (lane >> 2);
                bf[nt][0] = Bs[kk * 8 + (lane & 3)][cc];
                bf[nt][1] = Bs[kk * 8 + (lane & 3) + 4][cc];
            }
            #pragma unroll
            for (int mt = 0; mt < 4; mt++)
                #pragma unroll
                for (int nt = 0; nt < 4; nt++) {
                    asm volatile(
                        "mma.sync.aligned.m16n8k8.row.col.f32.tf32.tf32.f32 "
                        "{%0,%1,%2,%3}, {%4,%5,%6,%7}, {%8,%9}, {%0,%1,%2,%3};"
                        : "+f"(c[mt][nt][0]), "+f"(c[mt][nt][1]),
                          "+f"(c[mt][nt][2]), "+f"(c[mt][nt][3])
                        : "r"(af[mt][0]), "r"(af[mt][1]), "r"(af[mt][2]), "r"(af[mt][3]),
                          "r"(bf[nt][0]), "r"(bf[nt][1]));
                }
        }
        __syncthreads();
    }

    const int l2 = (lane & 3) * 2;
    if (y == 2) {
        #pragma unroll
        for (int mt = 0; mt < 4; mt++) {
            #pragma unroll
            for (int nt = 0; nt < 4; nt++) {
                int r = row0 + wm * 64 + mt * 16 + (lane >> 2);
                int cc = wn * 32 + nt * 8 + l2;
                float2 b2 = *(const float2*)(biasv + cc);
                float2 v01 = make_float2(c[mt][nt][0] + b2.x, c[mt][nt][1] + b2.y);
                float2 v23 = make_float2(c[mt][nt][2] + b2.x, c[mt][nt][3] + b2.y);
                if (r < M)     *(float2*)(acc + (size_t)r * 128 + cc) = v01;
                if (r + 8 < M) *(float2*)(acc + (size_t)(r + 8) * 128 + cc) = v23;
            }
        }
    } else {
        // attention dot in-register: head == wn (C=32 aligns with warp col tile)
        const float* att = (y == 0) ? att_s : att_d;
        float* adst = (y == 0) ? g_as : g_ad;
        float2 attv[4];
        #pragma unroll
        for (int nt = 0; nt < 4; nt++)
            attv[nt] = *(const float2*)(att + wn * 32 + nt * 8 + l2);

        #pragma unroll
        for (int mt = 0; mt < 4; mt++) {
            int r = row0 + wm * 64 + mt * 16 + (lane >> 2);
            float p0 = 0.f, p1 = 0.f;
            #pragma unroll
            for (int nt = 0; nt < 4; nt++) {
                p0 = fmaf(c[mt][nt][0], attv[nt].x, fmaf(c[mt][nt][1], attv[nt].y, p0));
                p1 = fmaf(c[mt][nt][2], attv[nt].x, fmaf(c[mt][nt][3], attv[nt].y, p1));
                if (y == 0) {
                    int cc = wn * 32 + nt * 8 + l2;
                    if (r < M)
                        *(half2*)(g_xs_h + (size_t)r * 128 + cc) =
                            __floats2half2_rn(c[mt][nt][0], c[mt][nt][1]);
                    if (r + 8 < M)
                        *(half2*)(g_xs_h + (size_t)(r + 8) * 128 + cc) =
                            __floats2half2_rn(c[mt][nt][2], c[mt][nt][3]);
                }
            }
            p0 += __shfl_xor_sync(0xFFFFFFFFu, p0, 1);
            p0 += __shfl_xor_sync(0xFFFFFFFFu, p0, 2);
            p1 += __shfl_xor_sync(0xFFFFFFFFu, p1, 1);
            p1 += __shfl_xor_sync(0xFFFFFFFFu, p1, 2);
            if ((lane & 3) == 0) {
                if (r < M)     adst[r * 4 + wn] = p0;
                if (r + 8 < M) adst[(r + 8) * 4 + wn] = p1;
            }
        }
    }
}

// ------------------------- fused edge softmax + SpMM (+LN) ---------------
__device__ __forceinline__ float lrelu_exp(float v)
{
    v = v > 0.f ? v : LRELU * v;
    return __expf(v);
}

template <bool DO_LN>
__global__ __launch_bounds__(256) void edge_fused(float* __restrict__ io,
                                                  const float* __restrict__ gamma,
                                                  const float* __restrict__ beta,
                                                  int n)
{
    int node = (blockIdx.x * blockDim.x + threadIdx.x) >> 5;
    int lane = threadIdx.x & 31;
    if (node >= n) return;
    const int rs = g_rowptr[node], re = g_rowptr[node + 1];
    const float4 ad = *(const float4*)(g_ad + (size_t)node * 4);

    // phase 1: per-edge weights + denominator (lane-parallel over edges)
    float4 ds = make_float4(0.f, 0.f, 0.f, 0.f);
    for (int e = rs + lane; e < re; e += 32) {
        int s = g_csrc[e];
        float4 a = *(const float4*)(g_as + (size_t)s * 4);
        float4 w;
        w.x = lrelu_exp(a.x + ad.x);
        w.y = lrelu_exp(a.y + ad.y);
        w.z = lrelu_exp(a.z + ad.z);
        w.w = lrelu_exp(a.w + ad.w);
        *(float4*)(g_w + (size_t)e * 4) = w;
        ds.x += w.x; ds.y += w.y; ds.z += w.z; ds.w += w.w;
    }
    #pragma unroll
    for (int m = 16; m >= 1; m >>= 1) {
        ds.x += __shfl_xor_sync(0xFFFFFFFFu, ds.x, m);
        ds.y += __shfl_xor_sync(0xFFFFFFFFu, ds.y, m);
        ds.z += __shfl_xor_sync(0xFFFFFFFFu, ds.z, m);
        ds.w += __shfl_xor_sync(0xFFFFFFFFu, ds.w, m);
    }
    const int h = lane >> 3;
    const float inv = __fdividef(1.f, (&ds.x)[h] + 1e-16f);

    // phase 2: weighted gather of fp16 xs (warp-parallel over features)
    float4 a = make_float4(0.f, 0.f, 0.f, 0.f);
    #pragma unroll 4
    for (int e = rs; e < re; e++) {
        int s = g_csrc[e];
        float w = g_w[(size_t)e * 4 + h] * inv;
        uint2 raw = *(const uint2*)(g_xs_h + (size_t)s * 128 + lane * 4);
        float2 lo = __half22float2(*(half2*)&raw.x);
        float2 hi = __half22float2(*(half2*)&raw.y);
        a.x = fmaf(w, lo.x, a.x);
        a.y = fmaf(w, lo.y, a.y);
        a.z = fmaf(w, hi.x, a.z);
        a.w = fmaf(w, hi.y, a.w);
    }

    float4 o = *(const float4*)(io + (size_t)node * 128 + lane * 4);
    o.x += a.x; o.y += a.y; o.z += a.z; o.w += a.w;

    if (DO_LN) {
        float sum = o.x + o.y + o.z + o.w;
        float sq  = o.x * o.x + o.y * o.y + o.z * o.z + o.w * o.w;
        #pragma unroll
        for (int m = 1; m <= 16; m <<= 1) {
            sum += __shfl_xor_sync(0xFFFFFFFFu, sum, m);
            sq  += __shfl_xor_sync(0xFFFFFFFFu, sq, m);
        }
        float mean = sum * (1.f / 128.f);
        float var  = sq * (1.f / 128.f) - mean * mean;
        float rstd = rsqrtf(var + LN_EPS);
        float4 g4 = *(const float4*)(gamma + lane * 4);
        float4 b4 = *(const float4*)(beta + lane * 4);
        float4 r;
        r.x = fmaxf(0.f, (o.x - mean) * rstd * g4.x + b4.x);
        r.y = fmaxf(0.f, (o.y - mean) * rstd * g4.y + b4.y);
        r.z = fmaxf(0.f, (o.z - mean) * rstd * g4.z + b4.z);
        r.w = fmaxf(0.f, (o.w - mean) * rstd * g4.w + b4.w);
        *(float4*)(g_h + (size_t)node * 128 + lane * 4) = r;
    } else {
        *(float4*)(io + (size_t)node * 128 + lane * 4) = o;
    }
}

// ------------------------- driver ----------------------------------------
extern "C" void kernel_launch(void* const* d_in, const int* in_sizes, int n_in,
                              void* d_out, int out_size)
{
    const float* x        = (const float*)d_in[0];
    const int*   ei       = (const int*)  d_in[1];
    const float* W1_src   = (const float*)d_in[2];
    const float* W1_dst   = (const float*)d_in[3];
    const float* att1_src = (const float*)d_in[4];
    const float* att1_dst = (const float*)d_in[5];
    const float* b1       = (const float*)d_in[6];
    const float* Wl1      = (const float*)d_in[7];
    const float* bl1      = (const float*)d_in[8];
    const float* gamma    = (const float*)d_in[9];
    const float* beta     = (const float*)d_in[10];
    const float* W2_src   = (const float*)d_in[11];
    const float* W2_dst   = (const float*)d_in[12];
    const float* att2_src = (const float*)d_in[13];
    const float* att2_dst = (const float*)d_in[14];
    const float* b2       = (const float*)d_in[15];
    const float* Wl2      = (const float*)d_in[16];
    const float* bl2      = (const float*)d_in[17];
    float* out = (float*)d_out;

    const int n = NN;
    const int E = EE;
    const int* src = ei;
    const int* dst = ei + E;

    void* p;
    cudaGetSymbolAddress(&p, g_acc1);  float* acc1 = (float*)p;
    cudaGetSymbolAddress(&p, g_h);     float* hbuf = (float*)p;
    cudaGetSymbolAddress(&p, g_Wcat);  float* wcat = (float*)p;
    cudaGetSymbolAddress(&p, g_biasA); float* bias = (float*)p;
    void* cntp;
    cudaGetSymbolAddress(&cntp, g_cnt);

    dim3 gemm_grid((n + 127) / 128, 3);
    int node_blocks = (n * 32 + 255) / 256;
    int edge_blocks = (E + 255) / 256;

    // CSR build (reused by both layers)
    cudaMemsetAsync(cntp, 0, NN * sizeof(int));
    hist_k<<<edge_blocks, 256>>>(dst, E);
    scan_k<<<1, 1024>>>(E);
    scatter_k<<<edge_blocks, 256>>>(src, dst, E);

    pack_all<<<64, 256>>>(W1_src, W1_dst, Wl1, bl1, b1,
                          W2_src, W2_dst, Wl2, bl2, b2);

    // layer 1
    gemm_tf32<<<gemm_grid, 256>>>(x, acc1, wcat, bias, att1_src, att1_dst, n);
    edge_fused<true><<<node_blocks, 256>>>(acc1, gamma, beta, n);

    // layer 2
    gemm_tf32<<<gemm_grid, 256>>>(hbuf, out, wcat + 128 * NCAT, bias + 128,
                                  att2_src, att2_dst, n);
    edge_fused<false><<<node_blocks, 256>>>(out, nullptr, nullptr, n);
}